// round 4
// baseline (speedup 1.0000x reference)
#include <cuda_runtime.h>

#define T_LEN  32768
#define NROWS  1024
#define NT     512
#define NW     (NT / 32)            // 16 warps
#define IT     8                    // items per thread per chunk
#define CHUNK  (NT * IT)            // 4096 floats per chunk
#define CPR    (T_LEN / CHUNK)      // 8 chunks per row
#define GRID   256
#define RPB    (NROWS / GRID)       // 4 rows per block
#define FLAT   (RPB * CPR)          // 32 flat chunks per block

__device__ double g_partial[GRID];
__device__ unsigned int g_count;

__global__ void __launch_bounds__(NT, 2)
wass_kernel(const float* __restrict__ yp, const float* __restrict__ yt,
            float* __restrict__ out) {
    __shared__ float scan_scr[2][NW];   // ping-pong warp totals
    __shared__ double dscr[NW];
    __shared__ bool is_last;

    const int tid  = threadIdx.x;
    const int lane = tid & 31;
    const int wid  = tid >> 5;
    const long blockrow0 = (long)blockIdx.x * RPB;

    // Prefetch flat chunk 0 (2 float4 per tensor per thread).
    float4 pa0, pa1, ta0, ta1;
    {
        const float4* p4 = (const float4*)(yp + blockrow0 * T_LEN);
        const float4* t4 = (const float4*)(yt + blockrow0 * T_LEN);
        int v = tid * 2;
        pa0 = p4[v]; pa1 = p4[v + 1];
        ta0 = t4[v]; ta1 = t4[v + 1];
    }

    double dacc = 0.0;          // across rows
    float  acc  = 0.0f;         // per-row weighted accumulator
    float  carry_total = 0.0f;  // row cumsum carry

    #pragma unroll 4
    for (int f = 0; f < FLAT; f++) {
        const int cir = f & (CPR - 1);

        // Consume prefetched regs -> 8-element diff segment.
        float d[IT];
        d[0] = pa0.x - ta0.x;  d[1] = pa0.y - ta0.y;
        d[2] = pa0.z - ta0.z;  d[3] = pa0.w - ta0.w;
        d[4] = pa1.x - ta1.x;  d[5] = pa1.y - ta1.y;
        d[6] = pa1.z - ta1.z;  d[7] = pa1.w - ta1.w;

        // Prefetch flat chunk f+1 (crosses row boundaries).
        if (f + 1 < FLAT) {
            const int nf    = f + 1;
            const long nrow = blockrow0 + (nf / CPR);
            const int  ncir = nf & (CPR - 1);
            const float4* p4 = (const float4*)(yp + nrow * T_LEN);
            const float4* t4 = (const float4*)(yt + nrow * T_LEN);
            int v = ncir * (CHUNK / 4) + tid * 2;
            pa0 = p4[v]; pa1 = p4[v + 1];
            ta0 = t4[v]; ta1 = t4[v + 1];
        }

        // Per-thread segment sum (tree).
        float seg = ((d[0] + d[1]) + (d[2] + d[3]))
                  + ((d[4] + d[5]) + (d[6] + d[7]));

        // Warp inclusive scan of segment sums.
        float inc = seg;
        #pragma unroll
        for (int o = 1; o < 32; o <<= 1) {
            float y = __shfl_up_sync(0xffffffffu, inc, o);
            if (lane >= o) inc += y;
        }

        // Publish warp totals; ONE barrier; every warp scans them redundantly.
        float* scr = scan_scr[f & 1];
        if (lane == 31) scr[wid] = inc;
        __syncthreads();

        float wv = (lane < NW) ? scr[lane] : 0.0f;
        float ws = wv;
        #pragma unroll
        for (int o = 1; o < NW; o <<= 1) {
            float y = __shfl_up_sync(0xffffffffu, ws, o);
            if (lane >= o) ws += y;
        }
        // exclusive prefix of warp totals for this warp, and chunk total
        float wpref = __shfl_sync(0xffffffffu, ws, (wid == 0) ? 0 : (wid - 1));
        if (wid == 0) wpref = 0.0f;
        float ctotal = __shfl_sync(0xffffffffu, ws, NW - 1);

        float run = carry_total + wpref + (inc - seg);
        carry_total += ctotal;

        // Weighted |cumsum| accumulation.
        const int idx0 = cir * CHUNK + tid * IT;
        #pragma unroll
        for (int k = 0; k < IT; k++) {
            run += d[k];
            float w = (float)(T_LEN - (idx0 + k));
            acc = fmaf(fabsf(run), w, acc);
        }

        // Row boundary: fold into double, reset row state.
        if (cir == CPR - 1) {
            dacc += (double)acc;
            acc = 0.0f;
            carry_total = 0.0f;
        }
    }

    // Deterministic block reduction of dacc.
    #pragma unroll
    for (int o = 16; o > 0; o >>= 1)
        dacc += __shfl_down_sync(0xffffffffu, dacc, o);
    if (lane == 0) dscr[wid] = dacc;
    __syncthreads();
    if (wid == 0) {
        double v = (lane < NW) ? dscr[lane] : 0.0;
        #pragma unroll
        for (int o = 8; o > 0; o >>= 1)
            v += __shfl_down_sync(0xffffffffu, v, o);
        if (lane == 0) {
            g_partial[blockIdx.x] = v;
            __threadfence();
            unsigned int prev = atomicAdd(&g_count, 1u);
            is_last = (prev == (unsigned int)(gridDim.x - 1));
        }
    }
    __syncthreads();

    // Last block: final reduce of 256 partials (8 warps -> warp sums -> tid 0).
    if (is_last) {
        if (tid == 0) g_count = 0;   // reset for graph replay
        double v = (tid < GRID) ? g_partial[tid] : 0.0;
        #pragma unroll
        for (int o = 16; o > 0; o >>= 1)
            v += __shfl_down_sync(0xffffffffu, v, o);
        if (lane == 0) dscr[wid] = v;
        __syncthreads();
        if (tid == 0) {
            double x = 0.0;
            #pragma unroll
            for (int i = 0; i < GRID / 32; i++) x += dscr[i];
            double tc = (double)T_LEN * 16.0;           // T*C
            double scale = 2.0 / (tc * (tc + 1.0));
            out[0] = (float)((x / 64.0) * scale);       // mean over B=64
        }
    }
}

extern "C" void kernel_launch(void* const* d_in, const int* in_sizes, int n_in,
                              void* d_out, int out_size) {
    (void)in_sizes; (void)n_in; (void)out_size;
    const float* y_pred = (const float*)d_in[0];
    const float* y_true = (const float*)d_in[1];
    float* out = (float*)d_out;
    wass_kernel<<<GRID, NT>>>(y_pred, y_true, out);
}

// round 5
// speedup vs baseline: 1.0060x; 1.0060x over previous
#include <cuda_runtime.h>

#define T_LEN   32768
#define NROWS   1024
#define IT      16                      // items per lane per chunk
#define CELEMS  (32 * IT)               // 512 elements per warp-chunk
#define NCHUNK  (T_LEN / CELEMS)        // 64 chunks per row

__device__ double g_partial[NROWS];
__device__ unsigned int g_count;

__global__ void __launch_bounds__(32, 16)
wass_kernel(const float* __restrict__ yp, const float* __restrict__ yt,
            float* __restrict__ out) {
    __shared__ bool is_last;

    const int lane = threadIdx.x;
    const int row  = blockIdx.x;

    const float4* __restrict__ p4 = (const float4*)(yp + (long)row * T_LEN);
    const float4* __restrict__ t4 = (const float4*)(yt + (long)row * T_LEN);

    // Prefetch chunk 0: 4 float4 per tensor per lane (8 independent LDG.128).
    float4 P0, P1, P2, P3, Q0, Q1, Q2, Q3;
    {
        int v = lane * 4;
        P0 = p4[v]; P1 = p4[v + 1]; P2 = p4[v + 2]; P3 = p4[v + 3];
        Q0 = t4[v]; Q1 = t4[v + 1]; Q2 = t4[v + 2]; Q3 = t4[v + 3];
    }

    double dacc = 0.0;
    float  carry = 0.0f;

    #pragma unroll 2
    for (int f = 0; f < NCHUNK; f++) {
        // Consume prefetched regs -> 16-element diff segment.
        float d[IT];
        d[0]  = P0.x - Q0.x; d[1]  = P0.y - Q0.y; d[2]  = P0.z - Q0.z; d[3]  = P0.w - Q0.w;
        d[4]  = P1.x - Q1.x; d[5]  = P1.y - Q1.y; d[6]  = P1.z - Q1.z; d[7]  = P1.w - Q1.w;
        d[8]  = P2.x - Q2.x; d[9]  = P2.y - Q2.y; d[10] = P2.z - Q2.z; d[11] = P2.w - Q2.w;
        d[12] = P3.x - Q3.x; d[13] = P3.y - Q3.y; d[14] = P3.z - Q3.z; d[15] = P3.w - Q3.w;

        // Prefetch next chunk immediately (loads in flight during scan below).
        if (f + 1 < NCHUNK) {
            int v = (f + 1) * (CELEMS / 4) + lane * 4;
            P0 = p4[v]; P1 = p4[v + 1]; P2 = p4[v + 2]; P3 = p4[v + 3];
            Q0 = t4[v]; Q1 = t4[v + 1]; Q2 = t4[v + 2]; Q3 = t4[v + 3];
        }

        // Per-lane segment sum (tree).
        float s01 = (d[0]  + d[1])  + (d[2]  + d[3]);
        float s23 = (d[4]  + d[5])  + (d[6]  + d[7]);
        float s45 = (d[8]  + d[9])  + (d[10] + d[11]);
        float s67 = (d[12] + d[13]) + (d[14] + d[15]);
        float seg = (s01 + s23) + (s45 + s67);

        // Warp inclusive scan of segment sums.
        float inc = seg;
        #pragma unroll
        for (int o = 1; o < 32; o <<= 1) {
            float y = __shfl_up_sync(0xffffffffu, inc, o);
            if (lane >= o) inc += y;
        }
        float total = __shfl_sync(0xffffffffu, inc, 31);

        // Running cumsum start for this lane's segment.
        float run = carry + (inc - seg);
        carry += total;

        // Weighted |cumsum| accumulation (fold into double per chunk).
        const int idx0 = f * CELEMS + lane * IT;
        float acc = 0.0f;
        #pragma unroll
        for (int k = 0; k < IT; k++) {
            run += d[k];
            float w = (float)(T_LEN - (idx0 + k));
            acc = fmaf(fabsf(run), w, acc);
        }
        dacc += (double)acc;
    }

    // Warp reduction of dacc (deterministic).
    #pragma unroll
    for (int o = 16; o > 0; o >>= 1)
        dacc += __shfl_down_sync(0xffffffffu, dacc, o);
    if (lane == 0) {
        g_partial[row] = dacc;
        __threadfence();
        unsigned int prev = atomicAdd(&g_count, 1u);
        is_last = (prev == (unsigned int)(gridDim.x - 1));
    }
    __syncwarp();
    is_last = __shfl_sync(0xffffffffu, (int)is_last, 0);

    // Last block: final deterministic reduce of 1024 partials with one warp.
    if (is_last) {
        if (lane == 0) g_count = 0;   // reset for graph replay
        double v = 0.0;
        #pragma unroll
        for (int j = 0; j < NROWS / 32; j++)
            v += g_partial[lane * (NROWS / 32) + j];
        #pragma unroll
        for (int o = 16; o > 0; o >>= 1)
            v += __shfl_down_sync(0xffffffffu, v, o);
        if (lane == 0) {
            double tc = (double)T_LEN * 16.0;            // T*C
            double scale = 2.0 / (tc * (tc + 1.0));
            out[0] = (float)((v / 64.0) * scale);        // mean over B=64
        }
    }
}

extern "C" void kernel_launch(void* const* d_in, const int* in_sizes, int n_in,
                              void* d_out, int out_size) {
    (void)in_sizes; (void)n_in; (void)out_size;
    const float* y_pred = (const float*)d_in[0];
    const float* y_true = (const float*)d_in[1];
    float* out = (float*)d_out;
    wass_kernel<<<NROWS, 32>>>(y_pred, y_true, out);
}

// round 6
// speedup vs baseline: 1.0478x; 1.0416x over previous
#include <cuda_runtime.h>

#define T_LEN   32768
#define NROWS   1024
#define IT      16                      // items per lane per chunk
#define CELEMS  (32 * IT)               // 512 elements per warp-chunk
#define NCHUNK  (T_LEN / CELEMS)        // 64 chunks per row

__device__ double g_partial[NROWS];
__device__ unsigned int g_count;

__device__ __forceinline__ float4 ldcs4(const float4* p) {
    return __ldcs(p);
}

__global__ void __launch_bounds__(32, 16)
wass_kernel(const float* __restrict__ yp, const float* __restrict__ yt,
            float* __restrict__ out) {
    __shared__ bool is_last;

    const int lane = threadIdx.x;
    const int row  = blockIdx.x;

    const float4* __restrict__ p4 = (const float4*)(yp + (long)row * T_LEN);
    const float4* __restrict__ t4 = (const float4*)(yt + (long)row * T_LEN);

    // Double-buffered prefetch: 2 chunks (16 LDG.128 = 8KB/warp) in flight.
    float4 P[2][4], Q[2][4];
    {
        int v0 = lane * 4;
        int v1 = (CELEMS / 4) + lane * 4;
        #pragma unroll
        for (int j = 0; j < 4; j++) {
            P[0][j] = ldcs4(p4 + v0 + j);
            Q[0][j] = ldcs4(t4 + v0 + j);
        }
        #pragma unroll
        for (int j = 0; j < 4; j++) {
            P[1][j] = ldcs4(p4 + v1 + j);
            Q[1][j] = ldcs4(t4 + v1 + j);
        }
    }

    double dacc = 0.0;
    float  carry = 0.0f;

    #pragma unroll 2
    for (int f = 0; f < NCHUNK; f++) {
        const int b = f & 1;

        // Consume buffer b -> 16-element diff segment.
        float d[IT];
        #pragma unroll
        for (int j = 0; j < 4; j++) {
            d[4*j+0] = P[b][j].x - Q[b][j].x;
            d[4*j+1] = P[b][j].y - Q[b][j].y;
            d[4*j+2] = P[b][j].z - Q[b][j].z;
            d[4*j+3] = P[b][j].w - Q[b][j].w;
        }

        // Refill buffer b with chunk f+2 (keeps 2 chunks always in flight).
        if (f + 2 < NCHUNK) {
            int v = (f + 2) * (CELEMS / 4) + lane * 4;
            #pragma unroll
            for (int j = 0; j < 4; j++) {
                P[b][j] = ldcs4(p4 + v + j);
                Q[b][j] = ldcs4(t4 + v + j);
            }
        }

        // Tree prefix within the 16-element segment (depth ~4).
        float pr[IT];
        pr[0] = d[0];
        #pragma unroll
        for (int k = 1; k < IT; k++) pr[k] = pr[k-1] + d[k];
        // (compiler keeps this as chain; build pairwise tree manually for depth)
        // pairwise sums
        float s2[8], s4[4], s8[2];
        #pragma unroll
        for (int j = 0; j < 8; j++) s2[j] = d[2*j] + d[2*j+1];
        #pragma unroll
        for (int j = 0; j < 4; j++) s4[j] = s2[2*j] + s2[2*j+1];
        s8[0] = s4[0] + s4[1];  s8[1] = s4[2] + s4[3];
        float seg = s8[0] + s8[1];

        // Warp inclusive scan of segment sums.
        float inc = seg;
        #pragma unroll
        for (int o = 1; o < 32; o <<= 1) {
            float y = __shfl_up_sync(0xffffffffu, inc, o);
            if (lane >= o) inc += y;
        }
        float total = __shfl_sync(0xffffffffu, inc, 31);

        float base = carry + (inc - seg);   // exclusive prefix before this segment
        carry += total;

        // Weighted |cumsum| accumulation, 2 independent FMA accumulators.
        const int idx0 = f * CELEMS + lane * IT;
        const float w0 = (float)(T_LEN - idx0);
        float acc0 = 0.0f, acc1 = 0.0f;
        #pragma unroll
        for (int k = 0; k < IT; k += 2) {
            float r0 = base + pr[k];
            float r1 = base + pr[k+1];
            acc0 = fmaf(fabsf(r0), w0 - (float)k,     acc0);
            acc1 = fmaf(fabsf(r1), w0 - (float)(k+1), acc1);
        }
        dacc += (double)(acc0 + acc1);
    }

    // Warp reduction of dacc (deterministic).
    #pragma unroll
    for (int o = 16; o > 0; o >>= 1)
        dacc += __shfl_down_sync(0xffffffffu, dacc, o);
    if (lane == 0) {
        g_partial[row] = dacc;
        __threadfence();
        unsigned int prev = atomicAdd(&g_count, 1u);
        is_last = (prev == (unsigned int)(gridDim.x - 1));
    }
    __syncwarp();
    int last = __shfl_sync(0xffffffffu, (int)is_last, 0);

    // Last block: final deterministic reduce of 1024 partials with one warp.
    if (last) {
        if (lane == 0) g_count = 0;   // reset for graph replay
        double v = 0.0;
        #pragma unroll
        for (int j = 0; j < NROWS / 32; j++)
            v += g_partial[lane * (NROWS / 32) + j];
        #pragma unroll
        for (int o = 16; o > 0; o >>= 1)
            v += __shfl_down_sync(0xffffffffu, v, o);
        if (lane == 0) {
            double tc = (double)T_LEN * 16.0;            // T*C
            double scale = 2.0 / (tc * (tc + 1.0));
            out[0] = (float)((v / 64.0) * scale);        // mean over B=64
        }
    }
}

extern "C" void kernel_launch(void* const* d_in, const int* in_sizes, int n_in,
                              void* d_out, int out_size) {
    (void)in_sizes; (void)n_in; (void)out_size;
    const float* y_pred = (const float*)d_in[0];
    const float* y_true = (const float*)d_in[1];
    float* out = (float*)d_out;
    wass_kernel<<<NROWS, 32>>>(y_pred, y_true, out);
}

// round 7
// speedup vs baseline: 1.1292x; 1.0776x over previous
#include <cuda_runtime.h>
#include <cstdint>

#define T_LEN   32768
#define NROWS   1024
#define IT      16                      // items per lane per chunk
#define CELEMS  (32 * IT)               // 512 elements per chunk
#define NCHUNK  (T_LEN / CELEMS)        // 64 chunks per row
#define STAGES  4
#define F4C     128                     // float4 per tensor chunk
#define STAGE_F4 (2 * F4C)              // P + Q per stage
#define SMEM_F4  (STAGES * STAGE_F4)    // 1024 float4 = 16 KB

__device__ double g_partial[NROWS];
__device__ unsigned int g_count;

__device__ __forceinline__ void cp16(uint32_t dst, const float4* src) {
    asm volatile("cp.async.cg.shared.global [%0], [%1], 16;" :: "r"(dst), "l"(src));
}
__device__ __forceinline__ void cp_commit() {
    asm volatile("cp.async.commit_group;" ::: "memory");
}
template <int N>
__device__ __forceinline__ void cp_wait() {
    asm volatile("cp.async.wait_group %0;" :: "n"(N) : "memory");
}
__device__ __forceinline__ int swz(int v) { return v ^ ((v >> 3) & 7); }

__global__ void __launch_bounds__(32, 8)
wass_kernel(const float* __restrict__ yp, const float* __restrict__ yt,
            float* __restrict__ out) {
    __shared__ float4 smem[SMEM_F4];
    __shared__ bool is_last;

    const int lane = threadIdx.x;
    const int row  = blockIdx.x;

    const float4* __restrict__ p4 = (const float4*)(yp + (long)row * T_LEN);
    const float4* __restrict__ t4 = (const float4*)(yt + (long)row * T_LEN);
    const uint32_t sbase = (uint32_t)__cvta_generic_to_shared(smem);

    // Issue one stage: 4 cp.async per tensor per lane (16B each), one commit group.
    auto issue = [&](int stage, int chunk) {
        const int vbase = chunk * F4C;
        #pragma unroll
        for (int i = 0; i < 4; i++) {
            int v  = i * 32 + lane;
            int sw = swz(v);
            cp16(sbase + (uint32_t)(stage * STAGE_F4 + sw) * 16u,       p4 + vbase + v);
            cp16(sbase + (uint32_t)(stage * STAGE_F4 + F4C + sw) * 16u, t4 + vbase + v);
        }
        cp_commit();
    };

    // Prologue: fill stages 0..2 with chunks 0..2 (3 groups pending).
    issue(0, 0); issue(1, 1); issue(2, 2);

    double dacc = 0.0;
    float  carry = 0.0f;

    for (int fb = 0; fb < NCHUNK; fb += STAGES) {
        #pragma unroll
        for (int s = 0; s < STAGES; s++) {
            const int f = fb + s;

            cp_wait<STAGES - 2>();     // oldest group (chunk f) complete
            __syncwarp();              // cross-lane smem visibility

            // Refill the stage consumed last iteration with chunk f+3.
            const int nc = f + STAGES - 1;
            if (nc < NCHUNK) issue((s + STAGES - 1) & (STAGES - 1), nc);
            else             cp_commit();   // empty group keeps accounting exact

            // Consume stage s: lane reads 16 contiguous elements (4 float4).
            float d[IT];
            #pragma unroll
            for (int j = 0; j < 4; j++) {
                int v  = lane * 4 + j;
                int sw = swz(v);
                float4 Pj = smem[s * STAGE_F4 + sw];
                float4 Qj = smem[s * STAGE_F4 + F4C + sw];
                d[4*j+0] = Pj.x - Qj.x;
                d[4*j+1] = Pj.y - Qj.y;
                d[4*j+2] = Pj.z - Qj.z;
                d[4*j+3] = Pj.w - Qj.w;
            }

            // Per-lane inclusive prefix (serial) + segment total.
            float pr[IT];
            pr[0] = d[0];
            #pragma unroll
            for (int k = 1; k < IT; k++) pr[k] = pr[k-1] + d[k];
            float seg = pr[IT-1];

            // Warp inclusive scan of segment sums.
            float inc = seg;
            #pragma unroll
            for (int o = 1; o < 32; o <<= 1) {
                float y = __shfl_up_sync(0xffffffffu, inc, o);
                if (lane >= o) inc += y;
            }
            float total = __shfl_sync(0xffffffffu, inc, 31);

            float base = carry + (inc - seg);
            carry += total;

            // Weighted |cumsum| accumulation, 2 independent FMA chains.
            const int idx0 = f * CELEMS + lane * IT;
            const float w0 = (float)(T_LEN - idx0);
            float acc0 = 0.0f, acc1 = 0.0f;
            #pragma unroll
            for (int k = 0; k < IT; k += 2) {
                float r0 = base + pr[k];
                float r1 = base + pr[k+1];
                acc0 = fmaf(fabsf(r0), w0 - (float)k,       acc0);
                acc1 = fmaf(fabsf(r1), w0 - (float)(k + 1), acc1);
            }
            dacc += (double)(acc0 + acc1);
        }
    }

    // Warp reduction of dacc (deterministic).
    #pragma unroll
    for (int o = 16; o > 0; o >>= 1)
        dacc += __shfl_down_sync(0xffffffffu, dacc, o);
    if (lane == 0) {
        g_partial[row] = dacc;
        __threadfence();
        unsigned int prev = atomicAdd(&g_count, 1u);
        is_last = (prev == (unsigned int)(gridDim.x - 1));
    }
    __syncwarp();
    int last = __shfl_sync(0xffffffffu, (int)is_last, 0);

    // Last block: final deterministic reduce of 1024 partials with one warp.
    if (last) {
        if (lane == 0) g_count = 0;   // reset for graph replay
        double v = 0.0;
        #pragma unroll
        for (int j = 0; j < NROWS / 32; j++)
            v += g_partial[lane * (NROWS / 32) + j];
        #pragma unroll
        for (int o = 16; o > 0; o >>= 1)
            v += __shfl_down_sync(0xffffffffu, v, o);
        if (lane == 0) {
            double tc = (double)T_LEN * 16.0;            // T*C
            double scale = 2.0 / (tc * (tc + 1.0));
            out[0] = (float)((v / 64.0) * scale);        // mean over B=64
        }
    }
}

extern "C" void kernel_launch(void* const* d_in, const int* in_sizes, int n_in,
                              void* d_out, int out_size) {
    (void)in_sizes; (void)n_in; (void)out_size;
    const float* y_pred = (const float*)d_in[0];
    const float* y_true = (const float*)d_in[1];
    float* out = (float*)d_out;
    wass_kernel<<<NROWS, 32>>>(y_pred, y_true, out);
}